// round 5
// baseline (speedup 1.0000x reference)
#include <cuda_runtime.h>
#include <math.h>

#define NPTS 8192
#define MB   64
#define NBALL 128
#define DIM  64
#define NH   8
#define EHD  8
#define HID  256
#define EPSF 1.1920929e-07f

// ---------------- scratch (device globals; no allocation) ----------------
__device__ float g_xat[NH * NPTS * EHD];   // head-major rmsnorm(x)+rel
__device__ float g_keyst[NH * NBALL * EHD];// head-major ball key means
__device__ int   g_idx[NH * NPTS * 2];     // top-2 ball indices, [h][n][2]
__device__ float g_h[NPTS * DIM];          // x + attn out (residual stream)
__device__ float g_w1t[DIM * HID];         // w1 transposed [d][k]
__device__ float g_w2t[DIM * HID];         // w2 transposed [d][k]
__device__ float g_w3t[HID * DIM];         // w3 transposed [k][d]

// ---------------- K1: per-ball prep + weight transpose (fused) ----------------
__global__ void k_prep(const float* __restrict__ x,
                       const float* __restrict__ pos,
                       const float* __restrict__ n1w,
                       const float* __restrict__ w1,
                       const float* __restrict__ w2,
                       const float* __restrict__ w3) {
    int blk = blockIdx.x, tid = threadIdx.x;
    if (blk >= NBALL) {
        int i = (blk - NBALL) * 256 + tid;   // 0..16383
        int k = i >> 6, d = i & 63;
        g_w1t[d * HID + k] = w1[i];
        g_w2t[d * HID + k] = w2[i];
        int d3 = i >> 8, k3 = i & 255;
        g_w3t[k3 * DIM + d3] = w3[i];
        return;
    }
    __shared__ float xs[MB][DIM + 1];
    __shared__ float ps[MB][DIM + 1];
    __shared__ float pm[DIM];
    __shared__ float wsm[DIM];
    int b = blk;
    const float* xb = x + b * (MB * DIM);
    const float* pb = pos + b * (MB * DIM);
    for (int i = tid; i < MB * DIM; i += 256) {
        int r = i >> 6, d = i & 63;
        xs[r][d] = xb[i];
        ps[r][d] = pb[i];
    }
    if (tid < DIM) wsm[tid] = n1w[tid];
    __syncthreads();
    if (tid < DIM) {
        float s = 0.f;
        #pragma unroll
        for (int r = 0; r < MB; r++) s += ps[r][tid];
        pm[tid] = s * (1.f / MB);
    }
    __syncthreads();
    int r = tid >> 2, part = tid & 3, d0 = part * 16;
    float ss = 0.f;
    #pragma unroll
    for (int j = 0; j < 16; j++) { float v = xs[r][d0 + j]; ss += v * v; }
    ss += __shfl_xor_sync(0xffffffffu, ss, 1);
    ss += __shfl_xor_sync(0xffffffffu, ss, 2);
    float rs = rsqrtf(ss * (1.f / DIM) + EPSF);
    float vals[16];
    #pragma unroll
    for (int j = 0; j < 16; j++) {
        int d = d0 + j;
        vals[j] = xs[r][d] * rs * wsm[d] + ps[r][d] - pm[d];
    }
    #pragma unroll
    for (int j = 0; j < 16; j++) xs[r][d0 + j] = vals[j];
    {
        int n = b * MB + r;
        float* o0 = g_xat + (part * 2) * (NPTS * EHD) + n * EHD;
        float* o1 = o0 + NPTS * EHD;
        ((float4*)o0)[0] = make_float4(vals[0], vals[1], vals[2], vals[3]);
        ((float4*)o0)[1] = make_float4(vals[4], vals[5], vals[6], vals[7]);
        ((float4*)o1)[0] = make_float4(vals[8], vals[9], vals[10], vals[11]);
        ((float4*)o1)[1] = make_float4(vals[12], vals[13], vals[14], vals[15]);
    }
    __syncthreads();
    if (tid < DIM) {
        float s = 0.f;
        #pragma unroll
        for (int r2 = 0; r2 < MB; r2++) s += xs[r2][tid];
        g_keyst[(tid >> 3) * (NBALL * EHD) + b * EHD + (tid & 7)] = s * (1.f / MB);
    }
}

// ---------------- K2: routing (top-2 balls; 2 points per thread) ----------------
__global__ void k_route() {
    __shared__ float4 ks[NBALL * 2];   // this head's keys
    int g = blockIdx.x * 256 + threadIdx.x;   // 0..32767
    int h = g >> 12;                          // 4096 thread-slots per head
    int n = g & 4095;                         // handles n and n+4096
    const float4* kg = (const float4*)(g_keyst + h * (NBALL * EHD));
    for (int i = threadIdx.x; i < NBALL * 2; i += 256) ks[i] = kg[i];
    __syncthreads();
    const float4* qp = (const float4*)(g_xat + h * (NPTS * EHD) + n * EHD);
    const float4* qq = (const float4*)(g_xat + h * (NPTS * EHD) + (n + 4096) * EHD);
    float4 qa = qp[0], qb = qp[1];
    float4 ra = qq[0], rb = qq[1];
    float v0 = -3.4e38f, v1 = -3.4e38f, u0 = -3.4e38f, u1 = -3.4e38f;
    int i0 = 0, i1 = 0, j0 = 0, j1 = 0;
    #pragma unroll 2
    for (int b = 0; b < NBALL; b++) {
        float4 kA = ks[b * 2], kB = ks[b * 2 + 1];
        float s = qa.x * kA.x + qa.y * kA.y + qa.z * kA.z + qa.w * kA.w
                + qb.x * kB.x + qb.y * kB.y + qb.z * kB.z + qb.w * kB.w;
        float t = ra.x * kA.x + ra.y * kA.y + ra.z * kA.z + ra.w * kA.w
                + rb.x * kB.x + rb.y * kB.y + rb.z * kB.z + rb.w * kB.w;
        if (s > v0) { v1 = v0; i1 = i0; v0 = s; i0 = b; }
        else if (s > v1) { v1 = s; i1 = b; }
        if (t > u0) { u1 = u0; j1 = j0; u0 = t; j0 = b; }
        else if (t > u1) { u1 = t; j1 = b; }
    }
    int o0 = (h * NPTS + n) * 2;
    int o1 = (h * NPTS + n + 4096) * 2;
    g_idx[o0] = i0; g_idx[o0 + 1] = i1;
    g_idx[o1] = j0; g_idx[o1 + 1] = j1;
}

// ---------------- K3: attention (one warp per (n,h), coalesced lane-pair) ----
__global__ void k_attn(const float* __restrict__ x) {
    int n = blockIdx.x;
    int h = threadIdx.x >> 5, lane = threadIdx.x & 31;
    const float* hb = g_xat + h * (NPTS * EHD);
    const float4* qp = (const float4*)(hb + n * EHD);
    float4 qa = qp[0], qb = qp[1];
    float4 qh = (lane & 1) ? qb : qa;
    int base = (h * NPTS + n) * 2;
    int b0 = g_idx[base], b1 = g_idx[base + 1];
    const float4* p0 = (const float4*)(hb + b0 * (MB * EHD));
    const float4* p1 = (const float4*)(hb + b1 * (MB * EHD));
    const float scale = 0.35355339059327373f;  // 1/sqrt(8)

    float4 v[8];
    #pragma unroll
    for (int c = 0; c < 4; c++) v[c] = p0[c * 32 + lane];
    #pragma unroll
    for (int c = 0; c < 4; c++) v[4 + c] = p1[c * 32 + lane];

    float s[8];
    #pragma unroll
    for (int i = 0; i < 8; i++) {
        float part = qh.x * v[i].x + qh.y * v[i].y + qh.z * v[i].z + qh.w * v[i].w;
        s[i] = (part + __shfl_xor_sync(0xffffffffu, part, 1)) * scale;
    }
    float m = s[0];
    #pragma unroll
    for (int i = 1; i < 8; i++) m = fmaxf(m, s[i]);
    #pragma unroll
    for (int o = 16; o >= 1; o >>= 1) m = fmaxf(m, __shfl_xor_sync(0xffffffffu, m, o));
    float p[8], lsum = 0.f;
    #pragma unroll
    for (int i = 0; i < 8; i++) { p[i] = __expf(s[i] - m); lsum += p[i]; }
    #pragma unroll
    for (int o = 16; o >= 1; o >>= 1) lsum += __shfl_xor_sync(0xffffffffu, lsum, o);
    float inv = 2.f / lsum;   // every row counted twice across the warp

    float4 acc = make_float4(0.f, 0.f, 0.f, 0.f);
    #pragma unroll
    for (int i = 0; i < 8; i++) {
        acc.x += p[i] * v[i].x; acc.y += p[i] * v[i].y;
        acc.z += p[i] * v[i].z; acc.w += p[i] * v[i].w;
    }
    #pragma unroll
    for (int o = 2; o <= 16; o <<= 1) {
        acc.x += __shfl_xor_sync(0xffffffffu, acc.x, o);
        acc.y += __shfl_xor_sync(0xffffffffu, acc.y, o);
        acc.z += __shfl_xor_sync(0xffffffffu, acc.z, o);
        acc.w += __shfl_xor_sync(0xffffffffu, acc.w, o);
    }
    if (lane < 2) {
        int off = n * DIM + h * EHD + lane * 4;
        float4 xr = *(const float4*)(x + off);
        float4 o;
        o.x = xr.x + acc.x * inv;
        o.y = xr.y + acc.y * inv;
        o.z = xr.z + acc.z * inv;
        o.w = xr.w + acc.w * inv;
        *(float4*)(g_h + off) = o;
    }
}

// ---------------- K4: fused MLP (rmsnorm + dual GEMM + SwiGLU + down + res) --
// 16 rows per block, 256 threads, grid 512.
// NOTE: hs has NO +1 pad -> rows stay 16B-aligned for float4 access.
__global__ void k_mlp(const float* __restrict__ n2w,
                      const float* __restrict__ b1p,
                      const float* __restrict__ b2p,
                      const float* __restrict__ b3p,
                      float* __restrict__ y) {
    __shared__ float ts[16][DIM + 1];
    __shared__ float hs[16][HID];      // 16KB, row stride 1024B (float4-safe)
    int tid = threadIdx.x;
    int r0 = blockIdx.x * 16;
    // ---- rmsnorm: 16 threads per row, 4 dims each ----
    {
        int rr = tid >> 4, p = tid & 15;
        float4 hv = *(const float4*)(g_h + (r0 + rr) * DIM + p * 4);
        float ss = hv.x * hv.x + hv.y * hv.y + hv.z * hv.z + hv.w * hv.w;
        ss += __shfl_xor_sync(0xffffffffu, ss, 1);
        ss += __shfl_xor_sync(0xffffffffu, ss, 2);
        ss += __shfl_xor_sync(0xffffffffu, ss, 4);
        ss += __shfl_xor_sync(0xffffffffu, ss, 8);
        float rs = rsqrtf(ss * (1.f / DIM) + EPSF);
        float4 wv = *(const float4*)(n2w + p * 4);
        ts[rr][p * 4 + 0] = hv.x * rs * wv.x;
        ts[rr][p * 4 + 1] = hv.y * rs * wv.y;
        ts[rr][p * 4 + 2] = hv.z * rs * wv.z;
        ts[rr][p * 4 + 3] = hv.w * rs * wv.w;
    }
    __syncthreads();
    // ---- phase 1: dual GEMM + SwiGLU -> hs ----
    {
        int rg = tid >> 6;           // 0..3 -> rows rg*4..rg*4+3
        int k = (tid & 63) * 4;
        float a1[4][4], a2[4][4];
        #pragma unroll
        for (int rr = 0; rr < 4; rr++)
            #pragma unroll
            for (int c = 0; c < 4; c++) { a1[rr][c] = 0.f; a2[rr][c] = 0.f; }
        #pragma unroll 4
        for (int d = 0; d < DIM; d++) {
            float4 w1v = *(const float4*)(g_w1t + d * HID + k);
            float4 w2v = *(const float4*)(g_w2t + d * HID + k);
            #pragma unroll
            for (int rr = 0; rr < 4; rr++) {
                float tv = ts[rg * 4 + rr][d];
                a1[rr][0] += tv * w1v.x; a1[rr][1] += tv * w1v.y;
                a1[rr][2] += tv * w1v.z; a1[rr][3] += tv * w1v.w;
                a2[rr][0] += tv * w2v.x; a2[rr][1] += tv * w2v.y;
                a2[rr][2] += tv * w2v.z; a2[rr][3] += tv * w2v.w;
            }
        }
        float4 bb1 = *(const float4*)(b1p + k);
        float4 bb2 = *(const float4*)(b2p + k);
        #pragma unroll
        for (int rr = 0; rr < 4; rr++) {
            float u1x = a1[rr][0] + bb1.x, u1y = a1[rr][1] + bb1.y;
            float u1z = a1[rr][2] + bb1.z, u1w = a1[rr][3] + bb1.w;
            int row = rg * 4 + rr;
            float4 o;
            o.x = (a2[rr][0] + bb2.x) * u1x * (1.f / (1.f + __expf(-u1x)));
            o.y = (a2[rr][1] + bb2.y) * u1y * (1.f / (1.f + __expf(-u1y)));
            o.z = (a2[rr][2] + bb2.z) * u1z * (1.f / (1.f + __expf(-u1z)));
            o.w = (a2[rr][3] + bb2.w) * u1w * (1.f / (1.f + __expf(-u1w)));
            *(float4*)&hs[row][k] = o;
        }
    }
    __syncthreads();
    // ---- phase 2: down-proj + residual ----
    {
        int row = tid >> 4;          // 0..15
        int c = (tid & 15) * 4;      // 4 cols
        float o0 = 0.f, o1 = 0.f, o2 = 0.f, o3 = 0.f;
        #pragma unroll 4
        for (int kk = 0; kk < HID; kk += 4) {
            float4 hv = *(const float4*)&hs[row][kk];
            float4 w0 = *(const float4*)(g_w3t + (kk + 0) * DIM + c);
            float4 w1v = *(const float4*)(g_w3t + (kk + 1) * DIM + c);
            float4 w2v = *(const float4*)(g_w3t + (kk + 2) * DIM + c);
            float4 w3v = *(const float4*)(g_w3t + (kk + 3) * DIM + c);
            o0 += hv.x * w0.x + hv.y * w1v.x + hv.z * w2v.x + hv.w * w3v.x;
            o1 += hv.x * w0.y + hv.y * w1v.y + hv.z * w2v.y + hv.w * w3v.y;
            o2 += hv.x * w0.z + hv.y * w1v.z + hv.z * w2v.z + hv.w * w3v.z;
            o3 += hv.x * w0.w + hv.y * w1v.w + hv.z * w2v.w + hv.w * w3v.w;
        }
        float4 bv = *(const float4*)(b3p + c);
        int off = (r0 + row) * DIM + c;
        float4 hres = *(const float4*)(g_h + off);
        float4 o;
        o.x = hres.x + o0 + bv.x;
        o.y = hres.y + o1 + bv.y;
        o.z = hres.z + o2 + bv.z;
        o.w = hres.w + o3 + bv.w;
        *(float4*)(y + off) = o;
    }
}

// ---------------- launch ----------------
extern "C" void kernel_launch(void* const* d_in, const int* in_sizes, int n_in,
                              void* d_out, int out_size) {
    const float* x    = (const float*)d_in[0];
    const float* pos  = (const float*)d_in[1];
    const float* n1w  = (const float*)d_in[2];
    const float* n2w  = (const float*)d_in[3];
    const float* w1w  = (const float*)d_in[4];
    const float* w1b  = (const float*)d_in[5];
    const float* w2w  = (const float*)d_in[6];
    const float* w2b  = (const float*)d_in[7];
    const float* w3w  = (const float*)d_in[8];
    const float* w3b  = (const float*)d_in[9];
    float* y = (float*)d_out;

    k_prep<<<NBALL + 64, 256>>>(x, pos, n1w, w1w, w2w, w3w);
    k_route<<<(NPTS * NH / 2) / 256, 256>>>();
    k_attn<<<NPTS, 256>>>(x);
    k_mlp<<<NPTS / 16, 256>>>(n2w, w1b, w2b, w3b, y);
}

// round 6
// speedup vs baseline: 1.0476x; 1.0476x over previous
#include <cuda_runtime.h>
#include <math.h>

#define NPTS 8192
#define MB   64
#define NBALL 128
#define DIM  64
#define NH   8
#define EHD  8
#define HID  256
#define EPSF 1.1920929e-07f

// ---------------- scratch (device globals; no allocation) ----------------
__device__ float g_xat[NH * NPTS * EHD];   // head-major rmsnorm(x)+rel
__device__ float g_keyst[NH * NBALL * EHD];// head-major ball key means
__device__ int   g_idx[NH * NPTS * 2];     // top-2 ball indices, [h][n][2]
__device__ float g_h[NPTS * DIM];          // x + attn out (residual stream)
__device__ float g_hid[NPTS * HID];        // swiglu hidden
__device__ float g_w1t[DIM * HID];         // w1 transposed [d][k]
__device__ float g_w2t[DIM * HID];         // w2 transposed [d][k]
__device__ float g_w3t[HID * DIM];         // w3 transposed [k][d]

// ---------------- K1: per-ball prep + weight transpose (fused) ----------------
__global__ void k_prep(const float* __restrict__ x,
                       const float* __restrict__ pos,
                       const float* __restrict__ n1w,
                       const float* __restrict__ w1,
                       const float* __restrict__ w2,
                       const float* __restrict__ w3) {
    int blk = blockIdx.x, tid = threadIdx.x;
    if (blk >= NBALL) {
        int i = (blk - NBALL) * 256 + tid;   // 0..16383
        int k = i >> 6, d = i & 63;
        g_w1t[d * HID + k] = w1[i];
        g_w2t[d * HID + k] = w2[i];
        int d3 = i >> 8, k3 = i & 255;
        g_w3t[k3 * DIM + d3] = w3[i];
        return;
    }
    __shared__ float xs[MB][DIM + 1];
    __shared__ float ps[MB][DIM + 1];
    __shared__ float pm[DIM];
    __shared__ float wsm[DIM];
    int b = blk;
    const float* xb = x + b * (MB * DIM);
    const float* pb = pos + b * (MB * DIM);
    for (int i = tid; i < MB * DIM; i += 256) {
        int r = i >> 6, d = i & 63;
        xs[r][d] = xb[i];
        ps[r][d] = pb[i];
    }
    if (tid < DIM) wsm[tid] = n1w[tid];
    __syncthreads();
    if (tid < DIM) {
        float s = 0.f;
        #pragma unroll
        for (int r = 0; r < MB; r++) s += ps[r][tid];
        pm[tid] = s * (1.f / MB);
    }
    __syncthreads();
    int r = tid >> 2, part = tid & 3, d0 = part * 16;
    float ss = 0.f;
    #pragma unroll
    for (int j = 0; j < 16; j++) { float v = xs[r][d0 + j]; ss += v * v; }
    ss += __shfl_xor_sync(0xffffffffu, ss, 1);
    ss += __shfl_xor_sync(0xffffffffu, ss, 2);
    float rs = rsqrtf(ss * (1.f / DIM) + EPSF);
    float vals[16];
    #pragma unroll
    for (int j = 0; j < 16; j++) {
        int d = d0 + j;
        vals[j] = xs[r][d] * rs * wsm[d] + ps[r][d] - pm[d];
    }
    #pragma unroll
    for (int j = 0; j < 16; j++) xs[r][d0 + j] = vals[j];
    {
        int n = b * MB + r;
        float* o0 = g_xat + (part * 2) * (NPTS * EHD) + n * EHD;
        float* o1 = o0 + NPTS * EHD;
        ((float4*)o0)[0] = make_float4(vals[0], vals[1], vals[2], vals[3]);
        ((float4*)o0)[1] = make_float4(vals[4], vals[5], vals[6], vals[7]);
        ((float4*)o1)[0] = make_float4(vals[8], vals[9], vals[10], vals[11]);
        ((float4*)o1)[1] = make_float4(vals[12], vals[13], vals[14], vals[15]);
    }
    __syncthreads();
    if (tid < DIM) {
        float s = 0.f;
        #pragma unroll
        for (int r2 = 0; r2 < MB; r2++) s += xs[r2][tid];
        g_keyst[(tid >> 3) * (NBALL * EHD) + b * EHD + (tid & 7)] = s * (1.f / MB);
    }
}

// ---------------- K2: routing (top-2 balls), 512 blocks x 128 threads ------
__global__ void k_route() {
    __shared__ float4 ks[NBALL * 2];   // this head's keys (4KB)
    int h = blockIdx.x >> 6;                 // 64 blocks per head
    int n = (blockIdx.x & 63) * 128 + threadIdx.x;
    const float4* kg = (const float4*)(g_keyst + h * (NBALL * EHD));
    ks[threadIdx.x] = kg[threadIdx.x];
    ks[threadIdx.x + 128] = kg[threadIdx.x + 128];
    __syncthreads();
    const float4* qp = (const float4*)(g_xat + h * (NPTS * EHD) + n * EHD);
    float4 qa = qp[0], qb = qp[1];
    float v0 = -3.4e38f, v1 = -3.4e38f;
    int i0 = 0, i1 = 0;
    #pragma unroll 4
    for (int b = 0; b < NBALL; b++) {
        float4 kA = ks[b * 2], kB = ks[b * 2 + 1];
        float s = qa.x * kA.x + qa.y * kA.y + qa.z * kA.z + qa.w * kA.w
                + qb.x * kB.x + qb.y * kB.y + qb.z * kB.z + qb.w * kB.w;
        if (s > v0) { v1 = v0; i1 = i0; v0 = s; i0 = b; }
        else if (s > v1) { v1 = s; i1 = b; }
    }
    int o = (h * NPTS + n) * 2;
    g_idx[o] = i0;
    g_idx[o + 1] = i1;
}

// ---------------- K3: attention (one warp per (n,h), coalesced lane-pair) ----
__global__ void k_attn(const float* __restrict__ x) {
    int n = blockIdx.x;
    int h = threadIdx.x >> 5, lane = threadIdx.x & 31;
    const float* hb = g_xat + h * (NPTS * EHD);
    const float4* qp = (const float4*)(hb + n * EHD);
    float4 qa = qp[0], qb = qp[1];
    float4 qh = (lane & 1) ? qb : qa;
    int base = (h * NPTS + n) * 2;
    int b0 = g_idx[base], b1 = g_idx[base + 1];
    const float4* p0 = (const float4*)(hb + b0 * (MB * EHD));
    const float4* p1 = (const float4*)(hb + b1 * (MB * EHD));
    const float scale = 0.35355339059327373f;  // 1/sqrt(8)

    float4 v[8];
    #pragma unroll
    for (int c = 0; c < 4; c++) v[c] = p0[c * 32 + lane];
    #pragma unroll
    for (int c = 0; c < 4; c++) v[4 + c] = p1[c * 32 + lane];

    float s[8];
    #pragma unroll
    for (int i = 0; i < 8; i++) {
        float part = qh.x * v[i].x + qh.y * v[i].y + qh.z * v[i].z + qh.w * v[i].w;
        s[i] = (part + __shfl_xor_sync(0xffffffffu, part, 1)) * scale;
    }
    float m = s[0];
    #pragma unroll
    for (int i = 1; i < 8; i++) m = fmaxf(m, s[i]);
    #pragma unroll
    for (int o = 16; o >= 1; o >>= 1) m = fmaxf(m, __shfl_xor_sync(0xffffffffu, m, o));
    float p[8], lsum = 0.f;
    #pragma unroll
    for (int i = 0; i < 8; i++) { p[i] = __expf(s[i] - m); lsum += p[i]; }
    #pragma unroll
    for (int o = 16; o >= 1; o >>= 1) lsum += __shfl_xor_sync(0xffffffffu, lsum, o);
    float inv = 2.f / lsum;   // every row counted twice across the warp

    float4 acc = make_float4(0.f, 0.f, 0.f, 0.f);
    #pragma unroll
    for (int i = 0; i < 8; i++) {
        acc.x += p[i] * v[i].x; acc.y += p[i] * v[i].y;
        acc.z += p[i] * v[i].z; acc.w += p[i] * v[i].w;
    }
    #pragma unroll
    for (int o = 2; o <= 16; o <<= 1) {
        acc.x += __shfl_xor_sync(0xffffffffu, acc.x, o);
        acc.y += __shfl_xor_sync(0xffffffffu, acc.y, o);
        acc.z += __shfl_xor_sync(0xffffffffu, acc.z, o);
        acc.w += __shfl_xor_sync(0xffffffffu, acc.w, o);
    }
    if (lane < 2) {
        int off = n * DIM + h * EHD + lane * 4;
        float4 xr = *(const float4*)(x + off);
        float4 o;
        o.x = xr.x + acc.x * inv;
        o.y = xr.y + acc.y * inv;
        o.z = xr.z + acc.z * inv;
        o.w = xr.w + acc.w * inv;
        *(float4*)(g_h + off) = o;
    }
}

// ---------------- K4: rmsnorm + dual GEMM + SwiGLU (8x4 dual tile) ----------
// 32 rows x 256 cols per block; launch_bounds caps regs to 128 -> 2 blocks/SM
__global__ void __launch_bounds__(256, 2)
k_mlp1(const float* __restrict__ n2w,
       const float* __restrict__ b1p,
       const float* __restrict__ b2p) {
    __shared__ float ts[32][DIM + 1];
    int tid = threadIdx.x;
    int r0 = blockIdx.x * 32;
    {
        int rr = tid >> 3, p = tid & 7;
        const float* hr = g_h + (r0 + rr) * DIM + p * 8;
        float hv[8], ss = 0.f;
        #pragma unroll
        for (int j = 0; j < 8; j++) { hv[j] = hr[j]; ss += hv[j] * hv[j]; }
        ss += __shfl_xor_sync(0xffffffffu, ss, 1);
        ss += __shfl_xor_sync(0xffffffffu, ss, 2);
        ss += __shfl_xor_sync(0xffffffffu, ss, 4);
        float rs = rsqrtf(ss * (1.f / DIM) + EPSF);
        #pragma unroll
        for (int j = 0; j < 8; j++) ts[rr][p * 8 + j] = hv[j] * rs * n2w[p * 8 + j];
    }
    __syncthreads();
    int rg = tid >> 6;           // 0..3 -> rows rg*8..rg*8+7
    int k = (tid & 63) * 4;
    float a1[8][4], a2[8][4];
    #pragma unroll
    for (int rr = 0; rr < 8; rr++)
        #pragma unroll
        for (int c = 0; c < 4; c++) { a1[rr][c] = 0.f; a2[rr][c] = 0.f; }
    #pragma unroll 2
    for (int d = 0; d < DIM; d++) {
        float4 w1v = *(const float4*)(g_w1t + d * HID + k);
        float4 w2v = *(const float4*)(g_w2t + d * HID + k);
        #pragma unroll
        for (int rr = 0; rr < 8; rr++) {
            float tv = ts[rg * 8 + rr][d];
            a1[rr][0] += tv * w1v.x; a1[rr][1] += tv * w1v.y;
            a1[rr][2] += tv * w1v.z; a1[rr][3] += tv * w1v.w;
            a2[rr][0] += tv * w2v.x; a2[rr][1] += tv * w2v.y;
            a2[rr][2] += tv * w2v.z; a2[rr][3] += tv * w2v.w;
        }
    }
    float4 bb1 = *(const float4*)(b1p + k);
    float4 bb2 = *(const float4*)(b2p + k);
    #pragma unroll
    for (int rr = 0; rr < 8; rr++) {
        int row = r0 + rg * 8 + rr;
        float u1x = a1[rr][0] + bb1.x, u1y = a1[rr][1] + bb1.y;
        float u1z = a1[rr][2] + bb1.z, u1w = a1[rr][3] + bb1.w;
        float4 o;
        o.x = (a2[rr][0] + bb2.x) * u1x * (1.f / (1.f + __expf(-u1x)));
        o.y = (a2[rr][1] + bb2.y) * u1y * (1.f / (1.f + __expf(-u1y)));
        o.z = (a2[rr][2] + bb2.z) * u1z * (1.f / (1.f + __expf(-u1z)));
        o.w = (a2[rr][3] + bb2.w) * u1w * (1.f / (1.f + __expf(-u1w)));
        *(float4*)(g_hid + row * HID + k) = o;
    }
}

// ---------------- K5: down-proj + residual (4x4 thread tiles) ----------------
__global__ void k_mlp2(const float* __restrict__ b3p, float* __restrict__ y) {
    __shared__ float hs[32][HID];   // 32 KB
    int tid = threadIdx.x;          // 128 threads
    int r0 = blockIdx.x * 32;
    {
        const float4* src = (const float4*)(g_hid + r0 * HID);
        float4* dst = (float4*)&hs[0][0];
        for (int i = tid; i < 32 * HID / 4; i += 128) dst[i] = src[i];
    }
    __syncthreads();
    int rg = tid >> 4;        // 0..7 -> rows rg*4..rg*4+3
    int c = (tid & 15) * 4;   // 4 cols
    float a[4][4];
    #pragma unroll
    for (int rr = 0; rr < 4; rr++)
        #pragma unroll
        for (int cc = 0; cc < 4; cc++) a[rr][cc] = 0.f;
    #pragma unroll 8
    for (int kk = 0; kk < HID; kk++) {
        float4 wv = *(const float4*)(g_w3t + kk * DIM + c);
        #pragma unroll
        for (int rr = 0; rr < 4; rr++) {
            float tv = hs[rg * 4 + rr][kk];
            a[rr][0] += tv * wv.x; a[rr][1] += tv * wv.y;
            a[rr][2] += tv * wv.z; a[rr][3] += tv * wv.w;
        }
    }
    float4 bv = *(const float4*)(b3p + c);
    #pragma unroll
    for (int rr = 0; rr < 4; rr++) {
        int row = r0 + rg * 4 + rr;
        float4 hres = *(const float4*)(g_h + row * DIM + c);
        float4 o;
        o.x = hres.x + a[rr][0] + bv.x;
        o.y = hres.y + a[rr][1] + bv.y;
        o.z = hres.z + a[rr][2] + bv.z;
        o.w = hres.w + a[rr][3] + bv.w;
        *(float4*)(y + row * DIM + c) = o;
    }
}

// ---------------- launch ----------------
extern "C" void kernel_launch(void* const* d_in, const int* in_sizes, int n_in,
                              void* d_out, int out_size) {
    const float* x    = (const float*)d_in[0];
    const float* pos  = (const float*)d_in[1];
    const float* n1w  = (const float*)d_in[2];
    const float* n2w  = (const float*)d_in[3];
    const float* w1w  = (const float*)d_in[4];
    const float* w1b  = (const float*)d_in[5];
    const float* w2w  = (const float*)d_in[6];
    const float* w2b  = (const float*)d_in[7];
    const float* w3w  = (const float*)d_in[8];
    const float* w3b  = (const float*)d_in[9];
    float* y = (float*)d_out;

    k_prep<<<NBALL + 64, 256>>>(x, pos, n1w, w1w, w2w, w3w);
    k_route<<<512, 128>>>();
    k_attn<<<NPTS, 256>>>(x);
    k_mlp1<<<NPTS / 32, 256>>>(n2w, w1b, w2b);
    k_mlp2<<<NPTS / 32, 128>>>(w3b, y);
}

// round 7
// speedup vs baseline: 1.4973x; 1.4293x over previous
#include <cuda_runtime.h>
#include <math.h>
#include <stdint.h>

#define NPTS 8192
#define MB   64
#define NBALL 128
#define DIM  64
#define NH   8
#define EHD  8
#define HID  256
#define EPSF 1.1920929e-07f

// ---------------- scratch ----------------
__device__ float    g_xat[NH * NPTS * EHD];
__device__ float    g_keyst[NH * NBALL * EHD];
__device__ int      g_idx[NH * NPTS * 2];
__device__ float    g_h[NPTS * DIM];
__device__ float    g_hid[NPTS * HID];
__device__ uint32_t g_w1f[16384];   // tf32 B-frags: [n8:32][k8:8][r:2][lane:32]
__device__ uint32_t g_w2f[16384];
__device__ uint32_t g_w3f[16384];   // [n8:8][k8:32][r:2][lane:32]

__device__ __forceinline__ uint32_t f2tf32(float f) {
    uint32_t u;
    asm("cvt.rna.tf32.f32 %0, %1;" : "=r"(u) : "f"(f));
    return u;
}
__device__ __forceinline__ void mma_tf32(float* c, const uint32_t* a,
                                         uint32_t b0, uint32_t b1) {
    asm volatile(
        "mma.sync.aligned.m16n8k8.row.col.f32.tf32.tf32.f32 "
        "{%0,%1,%2,%3}, {%4,%5,%6,%7}, {%8,%9}, {%0,%1,%2,%3};"
        : "+f"(c[0]), "+f"(c[1]), "+f"(c[2]), "+f"(c[3])
        : "r"(a[0]), "r"(a[1]), "r"(a[2]), "r"(a[3]), "r"(b0), "r"(b1));
}

// ---------------- K1: ball prep + weight fragment build ----------------
__global__ void k_prep(const float* __restrict__ x,
                       const float* __restrict__ pos,
                       const float* __restrict__ n1w,
                       const float* __restrict__ w1,
                       const float* __restrict__ w2,
                       const float* __restrict__ w3) {
    int blk = blockIdx.x, tid = threadIdx.x;
    if (blk >= NBALL) {
        int grp = blk - NBALL;
        int i = (grp & 63) * 256 + tid;       // 0..16383
        int lane = i & 31, r = (i >> 5) & 1;
        if (grp < 64) {
            // w1f / w2f: B[k][n] = w(n,k), w is (256,64) row-major
            int k8 = (i >> 6) & 7, n8 = i >> 9;
            int k = k8 * 8 + (lane & 3) + r * 4;
            int n = n8 * 8 + (lane >> 2);
            g_w1f[i] = f2tf32(w1[n * DIM + k]);
            g_w2f[i] = f2tf32(w2[n * DIM + k]);
        } else {
            // w3f: B[k][n] = w3(n,k), w3 is (64,256) row-major
            int k8 = (i >> 6) & 31, n8 = i >> 11;
            int k = k8 * 8 + (lane & 3) + r * 4;
            int n = n8 * 8 + (lane >> 2);
            g_w3f[i] = f2tf32(w3[n * HID + k]);
        }
        return;
    }
    __shared__ float xs[MB][DIM + 1];
    __shared__ float ps[MB][DIM + 1];
    __shared__ float pm[DIM];
    __shared__ float wsm[DIM];
    int b = blk;
    const float* xb = x + b * (MB * DIM);
    const float* pb = pos + b * (MB * DIM);
    for (int i = tid; i < MB * DIM; i += 256) {
        int r = i >> 6, d = i & 63;
        xs[r][d] = xb[i];
        ps[r][d] = pb[i];
    }
    if (tid < DIM) wsm[tid] = n1w[tid];
    __syncthreads();
    if (tid < DIM) {
        float s = 0.f;
        #pragma unroll
        for (int r = 0; r < MB; r++) s += ps[r][tid];
        pm[tid] = s * (1.f / MB);
    }
    __syncthreads();
    int r = tid >> 2, part = tid & 3, d0 = part * 16;
    float ss = 0.f;
    #pragma unroll
    for (int j = 0; j < 16; j++) { float v = xs[r][d0 + j]; ss += v * v; }
    ss += __shfl_xor_sync(0xffffffffu, ss, 1);
    ss += __shfl_xor_sync(0xffffffffu, ss, 2);
    float rs = rsqrtf(ss * (1.f / DIM) + EPSF);
    float vals[16];
    #pragma unroll
    for (int j = 0; j < 16; j++) {
        int d = d0 + j;
        vals[j] = xs[r][d] * rs * wsm[d] + ps[r][d] - pm[d];
    }
    #pragma unroll
    for (int j = 0; j < 16; j++) xs[r][d0 + j] = vals[j];
    {
        int n = b * MB + r;
        float* o0 = g_xat + (part * 2) * (NPTS * EHD) + n * EHD;
        float* o1 = o0 + NPTS * EHD;
        ((float4*)o0)[0] = make_float4(vals[0], vals[1], vals[2], vals[3]);
        ((float4*)o0)[1] = make_float4(vals[4], vals[5], vals[6], vals[7]);
        ((float4*)o1)[0] = make_float4(vals[8], vals[9], vals[10], vals[11]);
        ((float4*)o1)[1] = make_float4(vals[12], vals[13], vals[14], vals[15]);
    }
    __syncthreads();
    if (tid < DIM) {
        float s = 0.f;
        #pragma unroll
        for (int r2 = 0; r2 < MB; r2++) s += xs[r2][tid];
        g_keyst[(tid >> 3) * (NBALL * EHD) + b * EHD + (tid & 7)] = s * (1.f / MB);
    }
}

// ---------------- K2: routing ----------------
__global__ void k_route() {
    __shared__ float4 ks[NBALL * 2];
    int h = blockIdx.x >> 6;
    int n = (blockIdx.x & 63) * 128 + threadIdx.x;
    const float4* kg = (const float4*)(g_keyst + h * (NBALL * EHD));
    ks[threadIdx.x] = kg[threadIdx.x];
    ks[threadIdx.x + 128] = kg[threadIdx.x + 128];
    __syncthreads();
    const float4* qp = (const float4*)(g_xat + h * (NPTS * EHD) + n * EHD);
    float4 qa = qp[0], qb = qp[1];
    float v0 = -3.4e38f, v1 = -3.4e38f;
    int i0 = 0, i1 = 0;
    #pragma unroll 4
    for (int b = 0; b < NBALL; b++) {
        float4 kA = ks[b * 2], kB = ks[b * 2 + 1];
        float s = qa.x * kA.x + qa.y * kA.y + qa.z * kA.z + qa.w * kA.w
                + qb.x * kB.x + qb.y * kB.y + qb.z * kB.z + qb.w * kB.w;
        if (s > v0) { v1 = v0; i1 = i0; v0 = s; i0 = b; }
        else if (s > v1) { v1 = s; i1 = b; }
    }
    int o = (h * NPTS + n) * 2;
    g_idx[o] = i0;
    g_idx[o + 1] = i1;
}

// ---------------- K3: attention ----------------
__global__ void k_attn(const float* __restrict__ x) {
    int n = blockIdx.x;
    int h = threadIdx.x >> 5, lane = threadIdx.x & 31;
    const float* hb = g_xat + h * (NPTS * EHD);
    const float4* qp = (const float4*)(hb + n * EHD);
    float4 qa = qp[0], qb = qp[1];
    float4 qh = (lane & 1) ? qb : qa;
    int base = (h * NPTS + n) * 2;
    int b0 = g_idx[base], b1 = g_idx[base + 1];
    const float4* p0 = (const float4*)(hb + b0 * (MB * EHD));
    const float4* p1 = (const float4*)(hb + b1 * (MB * EHD));
    const float scale = 0.35355339059327373f;

    float4 v[8];
    #pragma unroll
    for (int c = 0; c < 4; c++) v[c] = p0[c * 32 + lane];
    #pragma unroll
    for (int c = 0; c < 4; c++) v[4 + c] = p1[c * 32 + lane];

    float s[8];
    #pragma unroll
    for (int i = 0; i < 8; i++) {
        float part = qh.x * v[i].x + qh.y * v[i].y + qh.z * v[i].z + qh.w * v[i].w;
        s[i] = (part + __shfl_xor_sync(0xffffffffu, part, 1)) * scale;
    }
    float m = s[0];
    #pragma unroll
    for (int i = 1; i < 8; i++) m = fmaxf(m, s[i]);
    #pragma unroll
    for (int o = 16; o >= 1; o >>= 1) m = fmaxf(m, __shfl_xor_sync(0xffffffffu, m, o));
    float p[8], lsum = 0.f;
    #pragma unroll
    for (int i = 0; i < 8; i++) { p[i] = __expf(s[i] - m); lsum += p[i]; }
    #pragma unroll
    for (int o = 16; o >= 1; o >>= 1) lsum += __shfl_xor_sync(0xffffffffu, lsum, o);
    float inv = 2.f / lsum;

    float4 acc = make_float4(0.f, 0.f, 0.f, 0.f);
    #pragma unroll
    for (int i = 0; i < 8; i++) {
        acc.x += p[i] * v[i].x; acc.y += p[i] * v[i].y;
        acc.z += p[i] * v[i].z; acc.w += p[i] * v[i].w;
    }
    #pragma unroll
    for (int o = 2; o <= 16; o <<= 1) {
        acc.x += __shfl_xor_sync(0xffffffffu, acc.x, o);
        acc.y += __shfl_xor_sync(0xffffffffu, acc.y, o);
        acc.z += __shfl_xor_sync(0xffffffffu, acc.z, o);
        acc.w += __shfl_xor_sync(0xffffffffu, acc.w, o);
    }
    if (lane < 2) {
        int off = n * DIM + h * EHD + lane * 4;
        float4 xr = *(const float4*)(x + off);
        float4 o;
        o.x = xr.x + acc.x * inv;
        o.y = xr.y + acc.y * inv;
        o.z = xr.z + acc.z * inv;
        o.w = xr.w + acc.w * inv;
        *(float4*)(g_h + off) = o;
    }
}

// ---------------- K4: rmsnorm + dual tf32-MMA GEMM + SwiGLU ----------------
// 32 rows/CTA, 256 threads; warp w handles cols [w*32, w*32+32)
__global__ void k_mlp1(const float* __restrict__ n2w,
                       const float* __restrict__ b1p,
                       const float* __restrict__ b2p) {
    __shared__ uint32_t safr[2 * 8 * 4 * 32];   // A-frags [m16][k8][reg][lane]
    __shared__ float sb1[HID], sb2[HID];
    int tid = threadIdx.x;
    int r0 = blockIdx.x * 32;
    sb1[tid] = b1p[tid];
    sb2[tid] = b2p[tid];
    // rmsnorm: thread -> row rr, cols p*8..p*8+7; write A-fragments
    {
        int rr = tid >> 3, p = tid & 7;
        const float* hr = g_h + (r0 + rr) * DIM + p * 8;
        float hv[8], ss = 0.f;
        #pragma unroll
        for (int j = 0; j < 8; j++) { hv[j] = hr[j]; ss += hv[j] * hv[j]; }
        ss += __shfl_xor_sync(0xffffffffu, ss, 1);
        ss += __shfl_xor_sync(0xffffffffu, ss, 2);
        ss += __shfl_xor_sync(0xffffffffu, ss, 4);
        float rs = rsqrtf(ss * (1.f / DIM) + EPSF);
        int m16 = rr >> 4;
        #pragma unroll
        for (int j = 0; j < 8; j++) {
            int k = p * 8 + j;
            float tv = hv[j] * rs * n2w[k];
            int lane_t = ((rr & 7) << 2) | (k & 3);
            int reg = ((rr >> 3) & 1) | (((k >> 2) & 1) << 1);
            int k8 = k >> 3;
            safr[(((m16 * 8 + k8) * 4 + reg) << 5) + lane_t] = f2tf32(tv);
        }
    }
    __syncthreads();
    int warp = tid >> 5, lane = tid & 31;
    float c1[2][4][4], c2[2][4][4];
    #pragma unroll
    for (int m = 0; m < 2; m++)
        #pragma unroll
        for (int n = 0; n < 4; n++)
            #pragma unroll
            for (int j = 0; j < 4; j++) { c1[m][n][j] = 0.f; c2[m][n][j] = 0.f; }
    #pragma unroll
    for (int k8 = 0; k8 < 8; k8++) {
        uint32_t a[2][4];
        #pragma unroll
        for (int m = 0; m < 2; m++)
            #pragma unroll
            for (int j = 0; j < 4; j++)
                a[m][j] = safr[(((m * 8 + k8) * 4 + j) << 5) + lane];
        #pragma unroll
        for (int n8l = 0; n8l < 4; n8l++) {
            int n8 = warp * 4 + n8l;
            int bidx = (((n8 * 8 + k8) << 1) << 5) + lane;
            uint32_t b10 = g_w1f[bidx], b11 = g_w1f[bidx + 32];
            uint32_t b20 = g_w2f[bidx], b21 = g_w2f[bidx + 32];
            mma_tf32(c1[0][n8l], a[0], b10, b11);
            mma_tf32(c1[1][n8l], a[1], b10, b11);
            mma_tf32(c2[0][n8l], a[0], b20, b21);
            mma_tf32(c2[1][n8l], a[1], b20, b21);
        }
    }
    // epilogue: bias + SwiGLU, store hidden fp32
    #pragma unroll
    for (int m = 0; m < 2; m++) {
        #pragma unroll
        for (int n8l = 0; n8l < 4; n8l++) {
            int colb = warp * 32 + n8l * 8 + 2 * (lane & 3);
            float bb1a = sb1[colb], bb1b = sb1[colb + 1];
            float bb2a = sb2[colb], bb2b = sb2[colb + 1];
            #pragma unroll
            for (int half = 0; half < 2; half++) {
                int row = r0 + m * 16 + (lane >> 2) + half * 8;
                float u1a = c1[m][n8l][half * 2] + bb1a;
                float u1b = c1[m][n8l][half * 2 + 1] + bb1b;
                float ha = (c2[m][n8l][half * 2] + bb2a) * u1a * (1.f / (1.f + __expf(-u1a)));
                float hb = (c2[m][n8l][half * 2 + 1] + bb2b) * u1b * (1.f / (1.f + __expf(-u1b)));
                *(float2*)(g_hid + row * HID + colb) = make_float2(ha, hb);
            }
        }
    }
}

// ---------------- K5: down-proj tf32-MMA + residual ----------------
// 32 rows/CTA, 256 threads; warp w handles cols [w*8, w*8+8)
__global__ void k_mlp2(const float* __restrict__ b3p, float* __restrict__ y) {
    __shared__ uint32_t safr[2 * 32 * 4 * 32];   // 32KB A-frags
    int tid = threadIdx.x;
    int r0 = blockIdx.x * 32;
    // load hid tile -> tf32 A-fragments
    for (int idx = tid; idx < 32 * HID; idx += 256) {
        int row = idx >> 8, k = idx & 255;
        float v = g_hid[(r0 + row) * HID + k];
        int m16 = row >> 4;
        int lane_t = ((row & 7) << 2) | (k & 3);
        int reg = ((row >> 3) & 1) | (((k >> 2) & 1) << 1);
        int k8 = k >> 3;
        safr[(((m16 * 32 + k8) * 4 + reg) << 5) + lane_t] = f2tf32(v);
    }
    __syncthreads();
    int warp = tid >> 5, lane = tid & 31;
    float c[2][4];
    #pragma unroll
    for (int m = 0; m < 2; m++)
        #pragma unroll
        for (int j = 0; j < 4; j++) c[m][j] = 0.f;
    #pragma unroll 4
    for (int k8 = 0; k8 < 32; k8++) {
        uint32_t a[2][4];
        #pragma unroll
        for (int m = 0; m < 2; m++)
            #pragma unroll
            for (int j = 0; j < 4; j++)
                a[m][j] = safr[(((m * 32 + k8) * 4 + j) << 5) + lane];
        int bidx = (((warp * 32 + k8) << 1) << 5) + lane;
        uint32_t b0 = g_w3f[bidx], b1 = g_w3f[bidx + 32];
        mma_tf32(c[0], a[0], b0, b1);
        mma_tf32(c[1], a[1], b0, b1);
    }
    int colb = warp * 8 + 2 * (lane & 3);
    float bva = b3p[colb], bvb = b3p[colb + 1];
    #pragma unroll
    for (int m = 0; m < 2; m++) {
        #pragma unroll
        for (int half = 0; half < 2; half++) {
            int row = r0 + m * 16 + (lane >> 2) + half * 8;
            float2 hres = *(const float2*)(g_h + row * DIM + colb);
            float2 o;
            o.x = hres.x + c[m][half * 2] + bva;
            o.y = hres.y + c[m][half * 2 + 1] + bvb;
            *(float2*)(y + row * DIM + colb) = o;
        }
    }
}

// ---------------- launch ----------------
extern "C" void kernel_launch(void* const* d_in, const int* in_sizes, int n_in,
                              void* d_out, int out_size) {
    const float* x    = (const float*)d_in[0];
    const float* pos  = (const float*)d_in[1];
    const float* n1w  = (const float*)d_in[2];
    const float* n2w  = (const float*)d_in[3];
    const float* w1w  = (const float*)d_in[4];
    const float* w1b  = (const float*)d_in[5];
    const float* w2w  = (const float*)d_in[6];
    const float* w2b  = (const float*)d_in[7];
    const float* w3w  = (const float*)d_in[8];
    const float* w3b  = (const float*)d_in[9];
    float* y = (float*)d_out;

    k_prep<<<NBALL + 128, 256>>>(x, pos, n1w, w1w, w2w, w3w);
    k_route<<<512, 128>>>();
    k_attn<<<NPTS, 256>>>(x);
    k_mlp1<<<NPTS / 32, 256>>>(n2w, w1b, w2b);
    k_mlp2<<<NPTS / 32, 256>>>(w3b, y);
}

// round 8
// speedup vs baseline: 1.6026x; 1.0703x over previous
#include <cuda_runtime.h>
#include <math.h>
#include <stdint.h>

#define NPTS 8192
#define MB   64
#define NBALL 128
#define DIM  64
#define NH   8
#define EHD  8
#define HID  256
#define EPSF 1.1920929e-07f

// ---------------- scratch ----------------
__device__ float    g_xat[NH * NPTS * EHD];
__device__ float    g_keyst[NH * NBALL * EHD];
__device__ int      g_idx[NH * NPTS * 2];
__device__ float    g_h[NPTS * DIM];
__device__ float    g_hid[NPTS * HID];
// packed tf32 B-fragments, 4 words/lane = [k8even r0, k8even r1, k8odd r0, k8odd r1]
__device__ uint32_t g_w1p[16384];   // [n8:32][k8p:4][lane:32][word:4]
__device__ uint32_t g_w2p[16384];
__device__ uint32_t g_w3p[16384];   // [n8:8][k8p:16][lane:32][word:4]

__device__ __forceinline__ uint32_t f2tf32(float f) {
    uint32_t u;
    asm("cvt.rna.tf32.f32 %0, %1;" : "=r"(u) : "f"(f));
    return u;
}
__device__ __forceinline__ void mma_tf32(float* c, const uint32_t* a,
                                         uint32_t b0, uint32_t b1) {
    asm volatile(
        "mma.sync.aligned.m16n8k8.row.col.f32.tf32.tf32.f32 "
        "{%0,%1,%2,%3}, {%4,%5,%6,%7}, {%8,%9}, {%0,%1,%2,%3};"
        : "+f"(c[0]), "+f"(c[1]), "+f"(c[2]), "+f"(c[3])
        : "r"(a[0]), "r"(a[1]), "r"(a[2]), "r"(a[3]), "r"(b0), "r"(b1));
}

// ---------------- K1: ball prep + packed weight fragment build ----------------
__global__ void k_prep(const float* __restrict__ x,
                       const float* __restrict__ pos,
                       const float* __restrict__ n1w,
                       const float* __restrict__ w1,
                       const float* __restrict__ w2,
                       const float* __restrict__ w3) {
    int blk = blockIdx.x, tid = threadIdx.x;
    if (blk >= NBALL) {
        int grp = blk - NBALL;
        int i = (grp & 63) * 256 + tid;       // 0..16383
        int word = i & 3, lane = (i >> 2) & 31;
        int j = word >> 1, r = word & 1;
        if (grp < 64) {
            int k8p = (i >> 7) & 3, n8 = i >> 9;
            int k8 = k8p * 2 + j;
            int k = k8 * 8 + (lane & 3) + r * 4;
            int n = n8 * 8 + (lane >> 2);
            g_w1p[i] = f2tf32(w1[n * DIM + k]);
            g_w2p[i] = f2tf32(w2[n * DIM + k]);
        } else {
            int k8p = (i >> 7) & 15, n8 = i >> 11;
            int k8 = k8p * 2 + j;
            int k = k8 * 8 + (lane & 3) + r * 4;
            int n = n8 * 8 + (lane >> 2);
            g_w3p[i] = f2tf32(w3[n * HID + k]);
        }
        return;
    }
    __shared__ float xs[MB][DIM + 1];
    __shared__ float ps[MB][DIM + 1];
    __shared__ float pm[DIM];
    __shared__ float wsm[DIM];
    int b = blk;
    const float* xb = x + b * (MB * DIM);
    const float* pb = pos + b * (MB * DIM);
    for (int i = tid; i < MB * DIM; i += 256) {
        int r = i >> 6, d = i & 63;
        xs[r][d] = xb[i];
        ps[r][d] = pb[i];
    }
    if (tid < DIM) wsm[tid] = n1w[tid];
    __syncthreads();
    if (tid < DIM) {
        float s = 0.f;
        #pragma unroll
        for (int r = 0; r < MB; r++) s += ps[r][tid];
        pm[tid] = s * (1.f / MB);
    }
    __syncthreads();
    int r = tid >> 2, part = tid & 3, d0 = part * 16;
    float ss = 0.f;
    #pragma unroll
    for (int j = 0; j < 16; j++) { float v = xs[r][d0 + j]; ss += v * v; }
    ss += __shfl_xor_sync(0xffffffffu, ss, 1);
    ss += __shfl_xor_sync(0xffffffffu, ss, 2);
    float rs = rsqrtf(ss * (1.f / DIM) + EPSF);
    float vals[16];
    #pragma unroll
    for (int j = 0; j < 16; j++) {
        int d = d0 + j;
        vals[j] = xs[r][d] * rs * wsm[d] + ps[r][d] - pm[d];
    }
    #pragma unroll
    for (int j = 0; j < 16; j++) xs[r][d0 + j] = vals[j];
    {
        int n = b * MB + r;
        float* o0 = g_xat + (part * 2) * (NPTS * EHD) + n * EHD;
        float* o1 = o0 + NPTS * EHD;
        ((float4*)o0)[0] = make_float4(vals[0], vals[1], vals[2], vals[3]);
        ((float4*)o0)[1] = make_float4(vals[4], vals[5], vals[6], vals[7]);
        ((float4*)o1)[0] = make_float4(vals[8], vals[9], vals[10], vals[11]);
        ((float4*)o1)[1] = make_float4(vals[12], vals[13], vals[14], vals[15]);
    }
    __syncthreads();
    if (tid < DIM) {
        float s = 0.f;
        #pragma unroll
        for (int r2 = 0; r2 < MB; r2++) s += xs[r2][tid];
        g_keyst[(tid >> 3) * (NBALL * EHD) + b * EHD + (tid & 7)] = s * (1.f / MB);
    }
}

// ---------------- K2: routing ----------------
__global__ void k_route() {
    __shared__ float4 ks[NBALL * 2];
    int h = blockIdx.x >> 6;
    int n = (blockIdx.x & 63) * 128 + threadIdx.x;
    const float4* kg = (const float4*)(g_keyst + h * (NBALL * EHD));
    ks[threadIdx.x] = kg[threadIdx.x];
    ks[threadIdx.x + 128] = kg[threadIdx.x + 128];
    __syncthreads();
    const float4* qp = (const float4*)(g_xat + h * (NPTS * EHD) + n * EHD);
    float4 qa = qp[0], qb = qp[1];
    float v0 = -3.4e38f, v1 = -3.4e38f;
    int i0 = 0, i1 = 0;
    #pragma unroll 4
    for (int b = 0; b < NBALL; b++) {
        float4 kA = ks[b * 2], kB = ks[b * 2 + 1];
        float s = qa.x * kA.x + qa.y * kA.y + qa.z * kA.z + qa.w * kA.w
                + qb.x * kB.x + qb.y * kB.y + qb.z * kB.z + qb.w * kB.w;
        if (s > v0) { v1 = v0; i1 = i0; v0 = s; i0 = b; }
        else if (s > v1) { v1 = s; i1 = b; }
    }
    int o = (h * NPTS + n) * 2;
    g_idx[o] = i0;
    g_idx[o + 1] = i1;
}

// ---------------- K3: attention ----------------
__global__ void k_attn(const float* __restrict__ x) {
    int n = blockIdx.x;
    int h = threadIdx.x >> 5, lane = threadIdx.x & 31;
    const float* hb = g_xat + h * (NPTS * EHD);
    const float4* qp = (const float4*)(hb + n * EHD);
    float4 qa = qp[0], qb = qp[1];
    float4 qh = (lane & 1) ? qb : qa;
    int base = (h * NPTS + n) * 2;
    int b0 = g_idx[base], b1 = g_idx[base + 1];
    const float4* p0 = (const float4*)(hb + b0 * (MB * EHD));
    const float4* p1 = (const float4*)(hb + b1 * (MB * EHD));
    const float scale = 0.35355339059327373f;

    float4 v[8];
    #pragma unroll
    for (int c = 0; c < 4; c++) v[c] = p0[c * 32 + lane];
    #pragma unroll
    for (int c = 0; c < 4; c++) v[4 + c] = p1[c * 32 + lane];

    float s[8];
    #pragma unroll
    for (int i = 0; i < 8; i++) {
        float part = qh.x * v[i].x + qh.y * v[i].y + qh.z * v[i].z + qh.w * v[i].w;
        s[i] = (part + __shfl_xor_sync(0xffffffffu, part, 1)) * scale;
    }
    float m = s[0];
    #pragma unroll
    for (int i = 1; i < 8; i++) m = fmaxf(m, s[i]);
    #pragma unroll
    for (int o = 16; o >= 1; o >>= 1) m = fmaxf(m, __shfl_xor_sync(0xffffffffu, m, o));
    float p[8], lsum = 0.f;
    #pragma unroll
    for (int i = 0; i < 8; i++) { p[i] = __expf(s[i] - m); lsum += p[i]; }
    #pragma unroll
    for (int o = 16; o >= 1; o >>= 1) lsum += __shfl_xor_sync(0xffffffffu, lsum, o);
    float inv = 2.f / lsum;

    float4 acc = make_float4(0.f, 0.f, 0.f, 0.f);
    #pragma unroll
    for (int i = 0; i < 8; i++) {
        acc.x += p[i] * v[i].x; acc.y += p[i] * v[i].y;
        acc.z += p[i] * v[i].z; acc.w += p[i] * v[i].w;
    }
    #pragma unroll
    for (int o = 2; o <= 16; o <<= 1) {
        acc.x += __shfl_xor_sync(0xffffffffu, acc.x, o);
        acc.y += __shfl_xor_sync(0xffffffffu, acc.y, o);
        acc.z += __shfl_xor_sync(0xffffffffu, acc.z, o);
        acc.w += __shfl_xor_sync(0xffffffffu, acc.w, o);
    }
    if (lane < 2) {
        int off = n * DIM + h * EHD + lane * 4;
        float4 xr = *(const float4*)(x + off);
        float4 o;
        o.x = xr.x + acc.x * inv;
        o.y = xr.y + acc.y * inv;
        o.z = xr.z + acc.z * inv;
        o.w = xr.w + acc.w * inv;
        *(float4*)(g_h + off) = o;
    }
}

// ---------------- K4: rmsnorm + dual tf32-MMA GEMM + SwiGLU ----------------
// 64 rows/CTA, 512 threads (16 warps); warp w handles n8 {2w, 2w+1}
// A-frags smem layout: [m16:4][k8:8][lane:32][reg:4]  (LDS.128 per (m,k8))
__global__ void __launch_bounds__(512, 1)
k_mlp1(const float* __restrict__ n2w,
       const float* __restrict__ b1p,
       const float* __restrict__ b2p) {
    __shared__ uint32_t safr[4 * 8 * 32 * 4];   // 16KB
    __shared__ float sb1[HID], sb2[HID];
    int tid = threadIdx.x;
    int r0 = blockIdx.x * 64;
    if (tid < HID) { sb1[tid] = b1p[tid]; sb2[tid] = b2p[tid]; }
    // rmsnorm: thread -> row rr (0..63), cols p*8..p*8+7
    {
        int rr = tid >> 3, p = tid & 7;
        const float* hr = g_h + (r0 + rr) * DIM + p * 8;
        float hv[8], ss = 0.f;
        #pragma unroll
        for (int j = 0; j < 8; j++) { hv[j] = hr[j]; ss += hv[j] * hv[j]; }
        ss += __shfl_xor_sync(0xffffffffu, ss, 1);
        ss += __shfl_xor_sync(0xffffffffu, ss, 2);
        ss += __shfl_xor_sync(0xffffffffu, ss, 4);
        float rs = rsqrtf(ss * (1.f / DIM) + EPSF);
        int m16 = rr >> 4;
        #pragma unroll
        for (int j = 0; j < 8; j++) {
            int k = p * 8 + j;
            float tv = hv[j] * rs * n2w[k];
            int lane_t = ((rr & 7) << 2) | (j & 3);
            int reg = ((rr >> 3) & 1) | ((j >> 2) << 1);
            safr[(((m16 * 8 + p) * 32 + lane_t) << 2) + reg] = f2tf32(tv);
        }
    }
    __syncthreads();
    int warp = tid >> 5, lane = tid & 31;
    float c1[4][2][4], c2[4][2][4];
    #pragma unroll
    for (int m = 0; m < 4; m++)
        #pragma unroll
        for (int n = 0; n < 2; n++)
            #pragma unroll
            for (int j = 0; j < 4; j++) { c1[m][n][j] = 0.f; c2[m][n][j] = 0.f; }
    #pragma unroll
    for (int k8p = 0; k8p < 4; k8p++) {
        // B: one LDG.128 per (n8, matrix): words {k8e r0, k8e r1, k8o r0, k8o r1}
        uint4 b1v[2], b2v[2];
        #pragma unroll
        for (int ns = 0; ns < 2; ns++) {
            int n8 = warp * 2 + ns;
            int bi = (((n8 * 4 + k8p) * 32 + lane) << 2);
            b1v[ns] = *(const uint4*)(g_w1p + bi);
            b2v[ns] = *(const uint4*)(g_w2p + bi);
        }
        #pragma unroll
        for (int j = 0; j < 2; j++) {
            int k8 = k8p * 2 + j;
            uint32_t a[4][4];
            #pragma unroll
            for (int m = 0; m < 4; m++) {
                uint4 av = *(const uint4*)(safr + (((m * 8 + k8) * 32 + lane) << 2));
                a[m][0] = av.x; a[m][1] = av.y; a[m][2] = av.z; a[m][3] = av.w;
            }
            #pragma unroll
            for (int ns = 0; ns < 2; ns++) {
                uint32_t w10 = j ? b1v[ns].z : b1v[ns].x;
                uint32_t w11 = j ? b1v[ns].w : b1v[ns].y;
                uint32_t w20 = j ? b2v[ns].z : b2v[ns].x;
                uint32_t w21 = j ? b2v[ns].w : b2v[ns].y;
                #pragma unroll
                for (int m = 0; m < 4; m++) {
                    mma_tf32(c1[m][ns], a[m], w10, w11);
                    mma_tf32(c2[m][ns], a[m], w20, w21);
                }
            }
        }
    }
    // epilogue: bias + SwiGLU -> g_hid (fp32)
    #pragma unroll
    for (int m = 0; m < 4; m++) {
        #pragma unroll
        for (int ns = 0; ns < 2; ns++) {
            int colb = (warp * 2 + ns) * 8 + 2 * (lane & 3);
            float bb1a = sb1[colb], bb1b = sb1[colb + 1];
            float bb2a = sb2[colb], bb2b = sb2[colb + 1];
            #pragma unroll
            for (int half = 0; half < 2; half++) {
                int row = r0 + m * 16 + (lane >> 2) + half * 8;
                float u1a = c1[m][ns][half * 2] + bb1a;
                float u1b = c1[m][ns][half * 2 + 1] + bb1b;
                float ha = (c2[m][ns][half * 2] + bb2a) * u1a * (1.f / (1.f + __expf(-u1a)));
                float hb = (c2[m][ns][half * 2 + 1] + bb2b) * u1b * (1.f / (1.f + __expf(-u1b)));
                *(float2*)(g_hid + row * HID + colb) = make_float2(ha, hb);
            }
        }
    }
}

// ---------------- K5: down-proj tf32-MMA + residual ----------------
// 32 rows/CTA, 256 threads; warp w = n8 column w
// A-frags smem: [m16:2][k8:32][lane:32][reg:4]  (32KB)
__global__ void k_mlp2(const float* __restrict__ b3p, float* __restrict__ y) {
    __shared__ uint32_t safr[2 * 32 * 32 * 4];
    int tid = threadIdx.x;
    int r0 = blockIdx.x * 32;
    for (int idx = tid; idx < 32 * HID; idx += 256) {
        int row = idx >> 8, k = idx & 255;
        float v = g_hid[(r0 + row) * HID + k];
        int m16 = row >> 4;
        int lane_t = ((row & 7) << 2) | (k & 3);
        int reg = ((row >> 3) & 1) | (((k >> 2) & 1) << 1);
        int k8 = k >> 3;
        safr[(((m16 * 32 + k8) * 32 + lane_t) << 2) + reg] = f2tf32(v);
    }
    __syncthreads();
    int warp = tid >> 5, lane = tid & 31;
    float c[2][4];
    #pragma unroll
    for (int m = 0; m < 2; m++)
        #pragma unroll
        for (int j = 0; j < 4; j++) c[m][j] = 0.f;
    #pragma unroll 4
    for (int k8p = 0; k8p < 16; k8p++) {
        uint4 bv = *(const uint4*)(g_w3p + (((warp * 16 + k8p) * 32 + lane) << 2));
        #pragma unroll
        for (int j = 0; j < 2; j++) {
            int k8 = k8p * 2 + j;
            uint32_t w0 = j ? bv.z : bv.x;
            uint32_t w1 = j ? bv.w : bv.y;
            #pragma unroll
            for (int m = 0; m < 2; m++) {
                uint4 av = *(const uint4*)(safr + (((m * 32 + k8) * 32 + lane) << 2));
                uint32_t a[4] = {av.x, av.y, av.z, av.w};
                mma_tf32(c[m], a, w0, w1);
            }
        }
    }
    int colb = warp * 8 + 2 * (lane & 3);
    float bva = b3p[colb], bvb = b3p[colb + 1];
    #pragma unroll
    for (int m = 0; m < 2; m++) {
        #pragma unroll
        for (int half = 0; half < 2; half++) {
            int row = r0 + m * 16 + (lane >> 2) + half * 8;
            float2 hres = *(const float2*)(g_h + row * DIM + colb);
            float2 o;
            o.x = hres.x + c[m][half * 2] + bva;
            o.y = hres.y + c[m][half * 2 + 1] + bvb;
            *(float2*)(y + row * DIM + colb) = o;
        }
    }
}

// ---------------- launch ----------------
extern "C" void kernel_launch(void* const* d_in, const int* in_sizes, int n_in,
                              void* d_out, int out_size) {
    const float* x    = (const float*)d_in[0];
    const float* pos  = (const float*)d_in[1];
    const float* n1w  = (const float*)d_in[2];
    const float* n2w  = (const float*)d_in[3];
    const float* w1w  = (const float*)d_in[4];
    const float* w1b  = (const float*)d_in[5];
    const float* w2w  = (const float*)d_in[6];
    const float* w2b  = (const float*)d_in[7];
    const float* w3w  = (const float*)d_in[8];
    const float* w3b  = (const float*)d_in[9];
    float* y = (float*)d_out;

    k_prep<<<NBALL + 128, 256>>>(x, pos, n1w, w1w, w2w, w3w);
    k_route<<<512, 128>>>();
    k_attn<<<NPTS, 256>>>(x);
    k_mlp1<<<NPTS / 64, 512>>>(n2w, w1b, w2b);
    k_mlp2<<<NPTS / 32, 256>>>(w3b, y);
}